// round 5
// baseline (speedup 1.0000x reference)
#include <cuda_runtime.h>
#include <cuda_bf16.h>

#define FULL_MASK 0xFFFFFFFFu

// 4 lanes per row (8 bins each), 8 rows per warp.
// Owner-lane finalization with L1 reload of (wj, vj, vj1) to shrink live ranges.
__global__ __launch_bounds__(256)
void pwq_coupling_kernel(const float* __restrict__ x_b,
                         const float* __restrict__ W,
                         const float* __restrict__ V,
                         float* __restrict__ out,   // [0:n)=z, [n:2n)=log_det
                         int n)
{
    const int lane = threadIdx.x & 31;
    const int t    = lane & 3;                 // sublane within 4-lane segment
    const int warpGlobal = (blockIdx.x * blockDim.x + threadIdx.x) >> 5;
    const int row = warpGlobal * 8 + (lane >> 2);
    if (row >= n) return;                      // n % 8 == 0 -> warp-uniform

    const float* __restrict__ Wrow = W + (size_t)row * 32 + t * 8;
    const float* __restrict__ Vrow = V + (size_t)row * 33 + t * 8;

    // ---- loads, issued up front for MLP ----
    const float  x  = x_b[row];                    // 4 lanes same addr -> broadcast
    const float4 wa = *(const float4*)(Wrow);      // bins 8t..8t+3
    const float4 wb = *(const float4*)(Wrow + 4);  // bins 8t+4..8t+7
    const float v0 = Vrow[0];
    const float v1 = Vrow[1];
    const float v2 = Vrow[2];
    const float v3 = Vrow[3];
    const float v4 = Vrow[4];
    const float v5 = Vrow[5];
    const float v6 = Vrow[6];
    const float v7 = Vrow[7];

    // 9th vertex: next sublane's v0; sublane 3 loads V[row,32]
    float v8 = __shfl_down_sync(FULL_MASK, v0, 1, 4);
    if (t == 3) v8 = Vrow[8];

    // ---- local inclusive prefixes of widths ----
    const float pw1 = wa.x;
    const float pw2 = pw1 + wa.y;
    const float pw3 = pw2 + wa.z;
    const float pw4 = pw3 + wa.w;
    const float pw5 = pw4 + wb.x;
    const float pw6 = pw5 + wb.y;
    const float pw7 = pw6 + wb.z;
    const float pw8 = pw7 + wb.w;

    // ---- local inclusive prefixes of trapezoid areas ----
    const float pa1 = 0.5f * (v0 + v1) * wa.x;
    const float pa2 = pa1 + 0.5f * (v1 + v2) * wa.y;
    const float pa3 = pa2 + 0.5f * (v2 + v3) * wa.z;
    const float pa4 = pa3 + 0.5f * (v3 + v4) * wa.w;
    const float pa5 = pa4 + 0.5f * (v4 + v5) * wb.x;
    const float pa6 = pa5 + 0.5f * (v5 + v6) * wb.y;
    const float pa7 = pa6 + 0.5f * (v6 + v7) * wb.z;
    const float pa8 = pa7 + 0.5f * (v7 + v8) * wb.w;
    // v0..v8, wa, wb are dead past this point (reloaded from L1 if needed).

    // ---- segmented 4-lane scan of segment totals ----
    float cw = pw8, ca = pa8;
    #pragma unroll
    for (int d = 1; d < 4; d <<= 1) {
        const float tw = __shfl_up_sync(FULL_MASK, cw, d, 4);
        const float ta = __shfl_up_sync(FULL_MASK, ca, d, 4);
        if (t >= d) { cw += tw; ca += ta; }
    }
    const float bw = cw - pw8;                 // left edge of bin 8t
    const float ba = ca - pa8;                 // CDF at left edge of bin 8t

    // ---- bin search: count interior edges <= val across the row ----
    const float val = fminf(fmaxf(x, 0.0f), 0.9999f);
    const float vb  = val - bw;                // segment-local coordinate
    int cnt = (int)(vb >= pw1) + (int)(vb >= pw2)
            + (int)(vb >= pw3) + (int)(vb >= pw4)
            + (int)(vb >= pw5) + (int)(vb >= pw6)
            + (int)(vb >= pw7) + (int)(vb >= pw8);
    cnt += __shfl_xor_sync(FULL_MASK, cnt, 1, 4);
    cnt += __shfl_xor_sync(FULL_MASK, cnt, 2, 4);
    const int bin = min(cnt, 31);

    // ---- owner lane finalizes ----
    if (t == (bin >> 3)) {
        const int j = bin & 7;
        // Reload the 3 needed scalars: guaranteed L1 hits (same lines loaded above).
        const float wj  = Wrow[j];
        const float vj  = Vrow[j];
        const float vj1 = Vrow[j + 1];         // j+1 <= 8; t=3,j=7 -> V[row,32]

        // local exclusive prefixes at j (index 0 -> 0)
        const bool b1 = (j & 1), b2 = (j & 2), b4 = (j & 4);
        const float pwj = b4 ? (b2 ? (b1 ? pw7 : pw6) : (b1 ? pw5 : pw4))
                             : (b2 ? (b1 ? pw3 : pw2) : (b1 ? pw1 : 0.0f));
        const float paj = b4 ? (b2 ? (b1 ? pa7 : pa6) : (b1 ? pa5 : pa4))
                             : (b2 ? (b1 ? pa3 : pa2) : (b1 ? pa1 : 0.0f));

        const float edge_b = bw + pwj;
        const float alpha  = __fdividef(val - edge_b, wj + 1e-8f);
        const float dv     = vj1 - vj;
        const float z      = (ba + paj) + alpha * wj * (vj + 0.5f * alpha * dv);
        out[row]     = z;
        out[n + row] = __logf(vj + alpha * dv + 1e-8f);
    }
}

extern "C" void kernel_launch(void* const* d_in, const int* in_sizes, int n_in,
                              void* d_out, int out_size)
{
    const float* x_b = (const float*)d_in[0];
    const float* W   = (const float*)d_in[1];
    const float* V   = (const float*)d_in[2];
    float* out = (float*)d_out;

    const int n = in_sizes[0];
    const int rowsPerBlock = 64;               // 8 warps * 8 rows
    const int blocks = (n + rowsPerBlock - 1) / rowsPerBlock;
    pwq_coupling_kernel<<<blocks, 256>>>(x_b, W, V, out, n);
}